// round 9
// baseline (speedup 1.0000x reference)
#include <cuda_runtime.h>
#include <cuda_fp16.h>
#include <cstdint>
#include <math.h>

// ---------------- Problem constants ----------------
#define BATCH   2
#define SEQ     4096
#define NTOK    (BATCH * SEQ)      // 8192
#define DMODEL  768
#define DINNER  3072
#define NHEADS  48
#define DHEAD   64
#define NEXP    8
#define R3      256
#define R2      1024
#define KPROJ   (2 * DINNER + NHEADS)   // 6192
#define CHUNK   128
#define NCHUNK  (SEQ / CHUNK)           // 32
#define MAXROWS (NTOK * 2 + NEXP * 128) // 17408
#define MAXTILES (MAXROWS / 128)        // 136

// ---------------- Scratch (static device globals) ----------------
__device__ __half g_xn   [NTOK * DMODEL];
__device__ __half g_proj [NTOK * KPROJ];
__device__ __half g_y    [NTOK * DINNER];
__device__ float  g_x1   [NTOK * DMODEL];
__device__ __half g_x2n  [NTOK * DMODEL];
__device__ __half g_lat  [NTOK * R3];
__device__ __half g_moe  [NTOK * R2];
__device__ __half g_WinT  [KPROJ * DMODEL];
__device__ __half g_WoutT [DMODEL * DINNER];
__device__ __half g_WdownT[R3 * DMODEL];
__device__ __half g_GtE   [NEXP * R2 * R3];
__device__ __half g_WupT  [DMODEL * R2];
__device__ float g_cA   [BATCH * NHEADS * NCHUNK];
__device__ float g_cB   [BATCH * NHEADS * NCHUNK * DHEAD];
__device__ float g_carry[BATCH * NHEADS * NCHUNK * DHEAD];
__device__ int    g_cnt[NEXP];
__device__ int    g_off[NEXP + 1];
__device__ int    g_cur[NEXP];
__device__ int    g_tileexp[MAXTILES];
__device__ int    g_ntiles;
__device__ int    g_e01 [NTOK];
__device__ float2 g_p01 [NTOK];
__device__ int    g_rowtok[MAXROWS];
__device__ float  g_rowp [MAXROWS];
__device__ int    g_slot[NTOK * 2];
__device__ __half g_easgn[MAXROWS * R2];

// ---------------- small helpers ----------------
__device__ __forceinline__ uint32_t smem_u32(const void* p) {
    uint32_t a;
    asm("{ .reg .u64 t; cvta.to.shared.u64 t, %1; cvt.u32.u64 %0, t; }"
        : "=r"(a) : "l"(p));
    return a;
}
__device__ __forceinline__ void cp_async16(uint32_t saddr, const void* gaddr, uint32_t srcsize) {
    asm volatile("cp.async.cg.shared.global [%0], [%1], 16, %2;"
                 :: "r"(saddr), "l"(gaddr), "r"(srcsize) : "memory");
}
__device__ __forceinline__ void cp_commit() {
    asm volatile("cp.async.commit_group;" ::: "memory");
}
template <int N>
__device__ __forceinline__ void cp_wait() {
    asm volatile("cp.async.wait_group %0;" :: "n"(N) : "memory");
}
__device__ __forceinline__ void ldmatrix_x4(uint32_t* r, uint32_t addr) {
    asm volatile("ldmatrix.sync.aligned.m8n8.x4.shared.b16 {%0,%1,%2,%3}, [%4];"
                 : "=r"(r[0]), "=r"(r[1]), "=r"(r[2]), "=r"(r[3]) : "r"(addr));
}
__device__ __forceinline__ void mma16816h(uint32_t* c, const uint32_t* a, uint32_t b0, uint32_t b1) {
    asm volatile(
        "mma.sync.aligned.m16n8k16.row.col.f16.f16.f16.f16 "
        "{%0,%1}, {%2,%3,%4,%5}, {%6,%7}, {%0,%1};"
        : "+r"(c[0]), "+r"(c[1])
        : "r"(a[0]), "r"(a[1]), "r"(a[2]), "r"(a[3]), "r"(b0), "r"(b1));
}

__device__ __forceinline__ uint32_t sw_off(int row, int ch) {
    return (uint32_t)row * 64u + (uint32_t)((ch ^ ((row >> 1) & 3)) << 4);
}

// ---------------- Main HMMA GEMM: CTA 256x128x32, warp tile 64x64 ----------------
#define BM2 256
#define BN2 128
#define BK 32
#define STAGES 3
#define ST2_BYTES 24576                 // 16KB A + 8KB B
#define GEMM2_SMEM (STAGES * ST2_BYTES) // 73728
#define A2_BYTES 16384

// EPI: 0 = half plain, 1 = float resid + ls*acc, 2 = half 10*tanh(acc/10)
template <int EPI>
__global__ __launch_bounds__(256, 2) void hgemm(
    const __half* __restrict__ A, const __half* __restrict__ Bt, void* __restrict__ Cv,
    int N, int K, const float* __restrict__ resid, const float* __restrict__ ls)
{
    extern __shared__ char smem[];
    const uint32_t sbase = smem_u32(smem);
    const int tid = threadIdx.x;
    const int wid = tid >> 5, lane = tid & 31;
    const int warp_m = wid & 3, warp_n = wid >> 2;      // 4 x 2
    const int m0 = blockIdx.y * BM2, n0 = blockIdx.x * BN2;

    // A loads: thread t -> row t, chunks 0..3 (64B)
    const uint32_t offA[4] = { sw_off(tid, 0), sw_off(tid, 1), sw_off(tid, 2), sw_off(tid, 3) };
    const __half* Ag = A + (size_t)(m0 + tid) * K;
    // B loads: row = t>>1, chunk base (t&1)*2
    const int blrow = tid >> 1;
    const int bc0 = (tid & 1) * 2;
    const uint32_t offB0 = sw_off(blrow, bc0);
    const uint32_t offB1 = sw_off(blrow, bc0 + 1);
    const bool bok = (n0 + blrow) < N;
    const int brow = bok ? (n0 + blrow) : (N - 1);
    const __half* Bg = Bt + (size_t)brow * K + bc0 * 8;
    const uint32_t bsz = bok ? 16u : 0u;

    const int nT = K / BK;

    #pragma unroll
    for (int s = 0; s < STAGES - 1; s++) {
        const int k0 = s * BK;
        uint32_t sb = sbase + s * ST2_BYTES;
        #pragma unroll
        for (int i = 0; i < 4; i++)
            cp_async16(sb + offA[i], Ag + k0 + i * 8, 16u);
        cp_async16(sb + A2_BYTES + offB0, Bg + k0, bsz);
        cp_async16(sb + A2_BYTES + offB1, Bg + k0 + 8, bsz);
        cp_commit();
    }

    const int mat = lane >> 3;
    const int lrow8 = (mat & 1) * 8 + (lane & 7);
    const int lch = mat >> 1;

    uint32_t acc[4][8][2];
    #pragma unroll
    for (int i = 0; i < 4; i++)
        #pragma unroll
        for (int j = 0; j < 8; j++) { acc[i][j][0] = 0u; acc[i][j][1] = 0u; }

    for (int kt = 0; kt < nT; kt++) {
        cp_wait<STAGES - 2>();
        __syncthreads();
        const uint32_t sb = sbase + (kt % STAGES) * ST2_BYTES;

        #pragma unroll
        for (int kk = 0; kk < 2; kk++) {
            const int ch = kk * 2 + lch;
            uint32_t af[4][4];
            #pragma unroll
            for (int mt = 0; mt < 4; mt++) {
                int r = warp_m * 64 + mt * 16 + lrow8;
                ldmatrix_x4(af[mt], sb + sw_off(r, ch));
            }
            uint32_t bf[4][4];
            #pragma unroll
            for (int nt = 0; nt < 4; nt++) {
                int r = warp_n * 64 + nt * 16 + lrow8;
                ldmatrix_x4(bf[nt], sb + A2_BYTES + sw_off(r, ch));
            }
            #pragma unroll
            for (int mt = 0; mt < 4; mt++)
                #pragma unroll
                for (int n8 = 0; n8 < 8; n8++) {
                    int nt = n8 >> 1, sel = n8 & 1;
                    mma16816h(acc[mt][n8], af[mt], bf[nt][sel], bf[nt][sel + 2]);
                }
        }

        const int nk = kt + STAGES - 1;
        if (nk < nT) {
            const int k0 = nk * BK;
            uint32_t sw = sbase + (nk % STAGES) * ST2_BYTES;
            #pragma unroll
            for (int i = 0; i < 4; i++)
                cp_async16(sw + offA[i], Ag + k0 + i * 8, 16u);
            cp_async16(sw + A2_BYTES + offB0, Bg + k0, bsz);
            cp_async16(sw + A2_BYTES + offB1, Bg + k0 + 8, bsz);
        }
        cp_commit();
    }

    const int gq = lane >> 2, t4 = lane & 3;
    #pragma unroll
    for (int mt = 0; mt < 4; mt++) {
        #pragma unroll
        for (int n8 = 0; n8 < 8; n8++) {
            int col = n0 + warp_n * 64 + n8 * 8 + t4 * 2;
            if (col >= N) continue;
            int row0 = m0 + warp_m * 64 + mt * 16 + gq;
            #pragma unroll
            for (int h = 0; h < 2; h++) {
                int r = row0 + h * 8;
                __half2 hv = *(__half2*)&acc[mt][n8][h];
                if (EPI == 0) {
                    *(__half2*)((__half*)Cv + (size_t)r * N + col) = hv;
                } else if (EPI == 1) {
                    float2 v = __half22float2(hv);
                    float2 rv = *(const float2*)(resid + (size_t)r * N + col);
                    float2 lv = *(const float2*)(ls + col);
                    float2 o;
                    o.x = rv.x + lv.x * v.x;
                    o.y = rv.y + lv.y * v.y;
                    *(float2*)((float*)Cv + (size_t)r * N + col) = o;
                } else {
                    float2 v = __half22float2(hv);
                    v.x = 10.f * tanhf(v.x * 0.1f);
                    v.y = 10.f * tanhf(v.y * 0.1f);
                    *(__half2*)((__half*)Cv + (size_t)r * N + col) = __floats2half2_rn(v.x, v.y);
                }
            }
        }
    }
}

// ---------------- Grouped-MoE gather GEMM (128x128 tiles, fp16 accum) ----------------
#define STAGE_BYTES 16384
#define GEMM_SMEM (STAGES * STAGE_BYTES)

__global__ __launch_bounds__(256, 3) void hgemm_moe()
{
    const int tileIdx = blockIdx.y;
    if (tileIdx >= g_ntiles) return;

    extern __shared__ char smem[];
    const uint32_t sbase = smem_u32(smem);
    const int tid = threadIdx.x;
    const int wid = tid >> 5, lane = tid & 31;
    const int warp_m = wid & 1, warp_n = wid >> 1;
    const int m0 = tileIdx * 128, n0 = blockIdx.x * 128;

    const int e = g_tileexp[tileIdx];
    const int offE = g_off[e], cntE = g_cnt[e];
    const __half* Bbase = g_GtE + (size_t)e * R2 * R3;

    const int lrow = tid >> 1;
    const int c0 = (tid & 1) * 2;
    const uint32_t offA0 = sw_off(lrow, c0);
    const uint32_t offA1 = sw_off(lrow, c0 + 1);
    const bool avalid = (m0 + lrow - offE) < cntE;
    const int tok = avalid ? g_rowtok[m0 + lrow] : 0;
    const __half* Ag = g_lat + (size_t)tok * R3 + c0 * 8;
    const __half* Bg = Bbase + (size_t)(n0 + lrow) * R3 + c0 * 8;

    const int nT = R3 / BK;

    #pragma unroll
    for (int s = 0; s < STAGES - 1; s++) {
        const int k0 = s * BK;
        uint32_t sb = sbase + s * STAGE_BYTES;
        cp_async16(sb + offA0, Ag + k0, 16u);
        cp_async16(sb + offA1, Ag + k0 + 8, 16u);
        cp_async16(sb + 8192 + offA0, Bg + k0, 16u);
        cp_async16(sb + 8192 + offA1, Bg + k0 + 8, 16u);
        cp_commit();
    }

    const int mat = lane >> 3;
    const int lrow8 = (mat & 1) * 8 + (lane & 7);
    const int lch = mat >> 1;

    uint32_t acc[4][4][2];
    #pragma unroll
    for (int i = 0; i < 4; i++)
        #pragma unroll
        for (int j = 0; j < 4; j++) { acc[i][j][0] = 0u; acc[i][j][1] = 0u; }

    for (int kt = 0; kt < nT; kt++) {
        cp_wait<STAGES - 2>();
        __syncthreads();
        const uint32_t sb = sbase + (kt % STAGES) * STAGE_BYTES;

        #pragma unroll
        for (int kk = 0; kk < 2; kk++) {
            uint32_t af[4][4];
            #pragma unroll
            for (int mt = 0; mt < 4; mt++) {
                int r = warp_m * 64 + mt * 16 + lrow8;
                ldmatrix_x4(af[mt], sb + sw_off(r, kk * 2 + lch));
            }
            uint32_t bf[2][4];
            #pragma unroll
            for (int nt = 0; nt < 2; nt++) {
                int r = warp_n * 32 + nt * 16 + lrow8;
                ldmatrix_x4(bf[nt], sb + 8192 + sw_off(r, kk * 2 + lch));
            }
            #pragma unroll
            for (int mt = 0; mt < 4; mt++)
                #pragma unroll
                for (int n8 = 0; n8 < 4; n8++) {
                    int nt = n8 >> 1, sel = n8 & 1;
                    mma16816h(acc[mt][n8], af[mt], bf[nt][sel], bf[nt][sel + 2]);
                }
        }

        const int nk = kt + STAGES - 1;
        if (nk < nT) {
            const int k0 = nk * BK;
            uint32_t sw = sbase + (nk % STAGES) * STAGE_BYTES;
            cp_async16(sw + offA0, Ag + k0, 16u);
            cp_async16(sw + offA1, Ag + k0 + 8, 16u);
            cp_async16(sw + 8192 + offA0, Bg + k0, 16u);
            cp_async16(sw + 8192 + offA1, Bg + k0 + 8, 16u);
        }
        cp_commit();
    }

    const int gq = lane >> 2, t4 = lane & 3;
    #pragma unroll
    for (int mt = 0; mt < 4; mt++) {
        int row0 = m0 + warp_m * 64 + mt * 16 + gq;
        float pr[2];
        bool pv[2];
        #pragma unroll
        for (int h = 0; h < 2; h++) {
            int ri = row0 + h * 8;
            pv[h] = (ri - offE) < cntE;
            pr[h] = pv[h] ? g_rowp[ri] : 0.f;
        }
        #pragma unroll
        for (int n8 = 0; n8 < 4; n8++) {
            int col = n0 + warp_n * 32 + n8 * 8 + t4 * 2;
            #pragma unroll
            for (int h = 0; h < 2; h++) {
                if (!pv[h]) continue;
                int ri = row0 + h * 8;
                float2 v = __half22float2(*(__half2*)&acc[mt][n8][h]);
                *(__half2*)(g_easgn + (size_t)ri * R2 + col) =
                    __floats2half2_rn(pr[h] * v.x, pr[h] * v.y);
            }
        }
    }
}

// ---------------- weight transpose + fp16 cast ----------------
__global__ void transpose_cast(const float* __restrict__ in, __half* __restrict__ out,
                               int K, int N)
{
    __shared__ float t[32][33];
    int n0 = blockIdx.x * 32, k0 = blockIdx.y * 32;
    int tx = threadIdx.x, ty = threadIdx.y;
    #pragma unroll
    for (int i = 0; i < 4; i++) {
        int k = k0 + ty + 8 * i, n = n0 + tx;
        t[ty + 8 * i][tx] = (n < N && k < K) ? in[(size_t)k * N + n] : 0.f;
    }
    __syncthreads();
    #pragma unroll
    for (int i = 0; i < 4; i++) {
        int n = n0 + ty + 8 * i, k = k0 + tx;
        if (n < N && k < K) out[(size_t)n * K + k] = __float2half(t[tx][ty + 8 * i]);
    }
}

// batched per-expert transpose of G: [E][R3][R2] -> [E][R2][R3]
__global__ void transpose_cast_G(const float* __restrict__ in, __half* __restrict__ out)
{
    __shared__ float t[32][33];
    int e = blockIdx.z;
    const float* ge = in + (size_t)e * R3 * R2;
    __half* oe = out + (size_t)e * R2 * R3;
    int n0 = blockIdx.x * 32, k0 = blockIdx.y * 32;
    int tx = threadIdx.x, ty = threadIdx.y;
    #pragma unroll
    for (int i = 0; i < 4; i++) {
        int k = k0 + ty + 8 * i, n = n0 + tx;
        t[ty + 8 * i][tx] = ge[(size_t)k * R2 + n];
    }
    __syncthreads();
    #pragma unroll
    for (int i = 0; i < 4; i++) {
        int n = n0 + ty + 8 * i, k = k0 + tx;
        oe[(size_t)n * R3 + k] = __float2half(t[tx][ty + 8 * i]);
    }
}

// ---------------- RMSNorm ----------------
__global__ __launch_bounds__(256) void rmsnorm_kernel(
    const float* __restrict__ x, const float* __restrict__ w, __half* __restrict__ out)
{
    int t = blockIdx.x;
    const float* xr = x + (size_t)t * DMODEL;
    int tid = threadIdx.x;
    float v0 = xr[tid], v1 = xr[tid + 256], v2 = xr[tid + 512];
    float s = v0 * v0 + v1 * v1 + v2 * v2;
    #pragma unroll
    for (int o = 16; o; o >>= 1) s += __shfl_xor_sync(0xffffffffu, s, o);
    __shared__ float red[8];
    __shared__ float scale;
    int wid = tid >> 5, lane = tid & 31;
    if (lane == 0) red[wid] = s;
    __syncthreads();
    if (tid < 32) {
        float r = (tid < 8) ? red[tid] : 0.f;
        #pragma unroll
        for (int o = 4; o; o >>= 1) r += __shfl_xor_sync(0xffffffffu, r, o);
        if (tid == 0) scale = rsqrtf(r / (float)DMODEL + 1e-5f);
    }
    __syncthreads();
    float sc = scale;
    __half* orow = out + (size_t)t * DMODEL;
    orow[tid]       = __float2half(v0 * sc * w[tid]);
    orow[tid + 256] = __float2half(v1 * sc * w[tid + 256]);
    orow[tid + 512] = __float2half(v2 * sc * w[tid + 512]);
}

// ---------------- Chunked selective scan ----------------
__global__ __launch_bounds__(64) void scan_pass1(
    const __half* __restrict__ proj, const float* __restrict__ dt_bias)
{
    int c = blockIdx.x, bh = blockIdx.y;
    int b = bh / NHEADS, h = bh % NHEADS;
    int d = threadIdx.x;
    float bias = dt_bias[h];
    const __half* base = proj + (size_t)(b * SEQ + c * CHUNK) * KPROJ;
    float Aacc = 1.f, hl = 0.f;
    #pragma unroll 4
    for (int t = 0; t < CHUNK; t++) {
        float dt = __half2float(base[(size_t)t * KPROJ + 2 * DINNER + h]);
        float u  = __half2float(base[(size_t)t * KPROJ + h * DHEAD + d]);
        float alpha = 1.f / (1.f + __expf(dt + bias));
        hl = fmaf(alpha, hl, u);
        Aacc *= alpha;
    }
    int idx = bh * NCHUNK + c;
    if (d == 0) g_cA[idx] = Aacc;
    g_cB[(size_t)idx * DHEAD + d] = hl;
}

__global__ __launch_bounds__(64) void scan_pass2()
{
    int bh = blockIdx.x;
    int d = threadIdx.x;
    float hc = 0.f;
    #pragma unroll
    for (int c = 0; c < NCHUNK; c++) {
        int idx = bh * NCHUNK + c;
        g_carry[(size_t)idx * DHEAD + d] = hc;
        hc = fmaf(g_cA[idx], hc, g_cB[(size_t)idx * DHEAD + d]);
    }
}

__global__ __launch_bounds__(64) void scan_pass3(
    const __half* __restrict__ proj, const float* __restrict__ dt_bias,
    __half* __restrict__ y)
{
    int c = blockIdx.x, bh = blockIdx.y;
    int b = bh / NHEADS, h = bh % NHEADS;
    int d = threadIdx.x;
    float bias = dt_bias[h];
    const __half* base = proj + (size_t)(b * SEQ + c * CHUNK) * KPROJ;
    __half* yb = y + (size_t)(b * SEQ + c * CHUNK) * DINNER + h * DHEAD + d;
    float hl = g_carry[((size_t)bh * NCHUNK + c) * DHEAD + d];
    #pragma unroll 4
    for (int t = 0; t < CHUNK; t++) {
        float dt = __half2float(base[(size_t)t * KPROJ + 2 * DINNER + h]);
        float u  = __half2float(base[(size_t)t * KPROJ + h * DHEAD + d]);
        float z  = __half2float(base[(size_t)t * KPROJ + DINNER + h * DHEAD + d]);
        float alpha = 1.f / (1.f + __expf(dt + bias));
        hl = fmaf(alpha, hl, u);
        float sig = 1.f / (1.f + __expf(-z));
        float v = hl * z * sig;
        yb[(size_t)t * DINNER] = __float2half(10.f * tanhf(v * 0.1f));
    }
}

// ---------------- Router ----------------
__global__ __launch_bounds__(256) void router_kernel(
    const __half* __restrict__ x2n, const float* __restrict__ Wr)
{
    int t = blockIdx.x;
    int wid = threadIdx.x >> 5, lane = threadIdx.x & 31;
    const __half* xr = x2n + (size_t)t * DMODEL;
    float s = 0.f;
    for (int r = lane; r < DMODEL; r += 32)
        s = fmaf(__half2float(xr[r]), Wr[r * NEXP + wid], s);
    #pragma unroll
    for (int o = 16; o; o >>= 1) s += __shfl_xor_sync(0xffffffffu, s, o);
    __shared__ float logits[NEXP];
    if (lane == 0) logits[wid] = s * 2.0f;
    __syncthreads();
    if (threadIdx.x == 0) {
        float best = -1e30f; int bi = 0;
        #pragma unroll
        for (int e = 0; e < NEXP; e++)
            if (logits[e] > best) { best = logits[e]; bi = e; }
        float sec = -1e30f; int si = 0;
        #pragma unroll
        for (int e = 0; e < NEXP; e++)
            if (e != bi && logits[e] > sec) { sec = logits[e]; si = e; }
        float p0 = 1.f / (1.f + __expf(sec - best));
        float p1 = 1.f - p0;
        g_e01[t] = bi | (si << 8);
        g_p01[t] = make_float2(p0, p1);
        atomicAdd(&g_cnt[bi], 1);
        atomicAdd(&g_cnt[si], 1);
    }
}

__global__ void moe_zero()
{
    if (threadIdx.x < NEXP) g_cnt[threadIdx.x] = 0;
}

__global__ void moe_offsets()
{
    if (threadIdx.x == 0) {
        int acc = 0;
        for (int e = 0; e < NEXP; e++) {
            g_off[e] = acc;
            g_cur[e] = acc;
            int tiles = (g_cnt[e] + 127) / 128;
            for (int i = 0; i < tiles; i++) g_tileexp[acc / 128 + i] = e;
            acc += tiles * 128;
        }
        g_off[NEXP] = acc;
        g_ntiles = acc / 128;
    }
}

__global__ __launch_bounds__(256) void moe_assign()
{
    int t = blockIdx.x * 256 + threadIdx.x;
    if (t >= NTOK) return;
    int ee = g_e01[t];
    int e0 = ee & 0xff, e1 = (ee >> 8) & 0xff;
    float2 p = g_p01[t];
    int pos0 = atomicAdd(&g_cur[e0], 1);
    g_rowtok[pos0] = t; g_rowp[pos0] = p.x; g_slot[2 * t] = pos0;
    int pos1 = atomicAdd(&g_cur[e1], 1);
    g_rowtok[pos1] = t; g_rowp[pos1] = p.y; g_slot[2 * t + 1] = pos1;
}

__global__ __launch_bounds__(256) void moe_combine()
{
    int t = blockIdx.x;
    int s0 = g_slot[2 * t], s1 = g_slot[2 * t + 1];
    const __half2* r0 = (const __half2*)(g_easgn + (size_t)s0 * R2);
    const __half2* r1 = (const __half2*)(g_easgn + (size_t)s1 * R2);
    __half2* o = (__half2*)(g_moe + (size_t)t * R2);
    int i = threadIdx.x;
    #pragma unroll
    for (int j = 0; j < 2; j++) {
        int k = i + j * 256;
        float2 a = __half22float2(r0[k]);
        float2 b = __half22float2(r1[k]);
        o[k] = __floats2half2_rn(a.x + b.x, a.y + b.y);
    }
}

// ---------------- Host launcher ----------------
extern "C" void kernel_launch(void* const* d_in, const int* in_sizes, int n_in,
                              void* d_out, int out_size)
{
    const float* x        = (const float*)d_in[0];
    const float* rms1_w   = (const float*)d_in[1];
    const float* W_in     = (const float*)d_in[2];
    const float* dt_bias  = (const float*)d_in[3];
    const float* W_out    = (const float*)d_in[4];
    const float* ls1      = (const float*)d_in[5];
    const float* rms2_w   = (const float*)d_in[6];
    const float* W_down   = (const float*)d_in[7];
    const float* W_router = (const float*)d_in[8];
    const float* G        = (const float*)d_in[9];
    const float* W_up     = (const float*)d_in[10];
    const float* ls2      = (const float*)d_in[11];
    float* out = (float*)d_out;

    __half *xn, *proj, *y, *x2n, *lat, *moe;
    __half *WinT, *WoutT, *WdownT, *GtE, *WupT;
    float *x1;
    cudaGetSymbolAddress((void**)&xn,     g_xn);
    cudaGetSymbolAddress((void**)&proj,   g_proj);
    cudaGetSymbolAddress((void**)&y,      g_y);
    cudaGetSymbolAddress((void**)&x1,     g_x1);
    cudaGetSymbolAddress((void**)&x2n,    g_x2n);
    cudaGetSymbolAddress((void**)&lat,    g_lat);
    cudaGetSymbolAddress((void**)&moe,    g_moe);
    cudaGetSymbolAddress((void**)&WinT,   g_WinT);
    cudaGetSymbolAddress((void**)&WoutT,  g_WoutT);
    cudaGetSymbolAddress((void**)&WdownT, g_WdownT);
    cudaGetSymbolAddress((void**)&GtE,    g_GtE);
    cudaGetSymbolAddress((void**)&WupT,   g_WupT);

    cudaFuncSetAttribute(hgemm<0>, cudaFuncAttributeMaxDynamicSharedMemorySize, GEMM2_SMEM);
    cudaFuncSetAttribute(hgemm<1>, cudaFuncAttributeMaxDynamicSharedMemorySize, GEMM2_SMEM);
    cudaFuncSetAttribute(hgemm<2>, cudaFuncAttributeMaxDynamicSharedMemorySize, GEMM2_SMEM);
    cudaFuncSetAttribute(hgemm_moe, cudaFuncAttributeMaxDynamicSharedMemorySize, GEMM_SMEM);

    dim3 tb(32, 8);
    transpose_cast<<<dim3((KPROJ + 31) / 32, DMODEL / 32), tb>>>(W_in, WinT, DMODEL, KPROJ);
    rmsnorm_kernel<<<NTOK, 256>>>(x, rms1_w, xn);
    transpose_cast<<<dim3(DMODEL / 32, DINNER / 32), tb>>>(W_out, WoutT, DINNER, DMODEL);
    // proj = xn @ W_in  [8192, 6192]
    hgemm<0><<<dim3((KPROJ + BN2 - 1) / BN2, NTOK / BM2), 256, GEMM2_SMEM>>>(
        xn, WinT, proj, KPROJ, DMODEL, nullptr, nullptr);
    transpose_cast<<<dim3(R3 / 32, DMODEL / 32), tb>>>(W_down, WdownT, DMODEL, R3);
    transpose_cast<<<dim3(DMODEL / 32, R2 / 32), tb>>>(W_up, WupT, R2, DMODEL);
    transpose_cast_G<<<dim3(R2 / 32, R3 / 32, NEXP), tb>>>(G, GtE);

    scan_pass1<<<dim3(NCHUNK, BATCH * NHEADS), 64>>>(proj, dt_bias);
    scan_pass2<<<BATCH * NHEADS, 64>>>();
    scan_pass3<<<dim3(NCHUNK, BATCH * NHEADS), 64>>>(proj, dt_bias, y);
    hgemm<1><<<dim3(DMODEL / BN2, NTOK / BM2), 256, GEMM2_SMEM>>>(
        y, WoutT, x1, DMODEL, DINNER, x, ls1);
    rmsnorm_kernel<<<NTOK, 256>>>(x1, rms2_w, x2n);
    hgemm<2><<<dim3(R3 / BN2, NTOK / BM2), 256, GEMM2_SMEM>>>(
        x2n, WdownT, lat, R3, DMODEL, nullptr, nullptr);
    moe_zero<<<1, 32>>>();
    router_kernel<<<NTOK, 256>>>(x2n, W_router);
    moe_offsets<<<1, 32>>>();
    moe_assign<<<(NTOK + 255) / 256, 256>>>();
    hgemm_moe<<<dim3(R2 / 128, MAXTILES), 256, GEMM_SMEM>>>();
    moe_combine<<<NTOK, 256>>>();
    hgemm<1><<<dim3(DMODEL / BN2, NTOK / BM2), 256, GEMM2_SMEM>>>(
        moe, WupT, out, DMODEL, R2, x1, ls2);
}

// round 11
// speedup vs baseline: 1.1452x; 1.1452x over previous
#include <cuda_runtime.h>
#include <cuda_fp16.h>
#include <cstdint>
#include <math.h>

// ---------------- Problem constants ----------------
#define BATCH   2
#define SEQ     4096
#define NTOK    (BATCH * SEQ)      // 8192
#define DMODEL  768
#define DINNER  3072
#define NHEADS  48
#define DHEAD   64
#define NEXP    8
#define R3      256
#define R2      1024
#define KPROJ   (2 * DINNER + NHEADS)   // 6192
#define CHUNK   128
#define NCHUNK  (SEQ / CHUNK)           // 32
#define MAXROWS (NTOK * 2 + NEXP * 128) // 17408
#define MAXTILES (MAXROWS / 128)        // 136

// ---------------- Scratch (static device globals) ----------------
__device__ __half g_xn   [NTOK * DMODEL];
__device__ __half g_proj [NTOK * KPROJ];
__device__ __half g_y    [NTOK * DINNER];
__device__ float  g_x1   [NTOK * DMODEL];
__device__ __half g_x2n  [NTOK * DMODEL];
__device__ __half g_lat  [NTOK * R3];
__device__ __half g_moe  [NTOK * R2];
__device__ __half g_WinT  [KPROJ * DMODEL];
__device__ __half g_WoutT [DMODEL * DINNER];
__device__ __half g_WdownT[R3 * DMODEL];
__device__ __half g_GtE   [NEXP * R2 * R3];
__device__ __half g_WupT  [DMODEL * R2];
__device__ float g_cA   [BATCH * NHEADS * NCHUNK];
__device__ float g_cB   [BATCH * NHEADS * NCHUNK * DHEAD];
__device__ float g_carry[BATCH * NHEADS * NCHUNK * DHEAD];
__device__ int    g_cnt[NEXP];
__device__ int    g_off[NEXP + 1];
__device__ int    g_cur[NEXP];
__device__ int    g_tileexp[MAXTILES];
__device__ int    g_ntiles;
__device__ int    g_e01 [NTOK];
__device__ float2 g_p01 [NTOK];
__device__ int    g_rowtok[MAXROWS];
__device__ float  g_rowp [MAXROWS];
__device__ int    g_slot[NTOK * 2];
__device__ __half g_easgn[MAXROWS * R2];

// ---------------- small helpers ----------------
__device__ __forceinline__ uint32_t smem_u32(const void* p) {
    uint32_t a;
    asm("{ .reg .u64 t; cvta.to.shared.u64 t, %1; cvt.u32.u64 %0, t; }"
        : "=r"(a) : "l"(p));
    return a;
}
__device__ __forceinline__ void cp_async16(uint32_t saddr, const void* gaddr, uint32_t srcsize) {
    asm volatile("cp.async.cg.shared.global [%0], [%1], 16, %2;"
                 :: "r"(saddr), "l"(gaddr), "r"(srcsize) : "memory");
}
__device__ __forceinline__ void cp_commit() {
    asm volatile("cp.async.commit_group;" ::: "memory");
}
template <int N>
__device__ __forceinline__ void cp_wait() {
    asm volatile("cp.async.wait_group %0;" :: "n"(N) : "memory");
}
__device__ __forceinline__ void ldmatrix_x4(uint32_t* r, uint32_t addr) {
    asm volatile("ldmatrix.sync.aligned.m8n8.x4.shared.b16 {%0,%1,%2,%3}, [%4];"
                 : "=r"(r[0]), "=r"(r[1]), "=r"(r[2]), "=r"(r[3]) : "r"(addr));
}
__device__ __forceinline__ void mma16816h(uint32_t* c, const uint32_t* a, uint32_t b0, uint32_t b1) {
    asm volatile(
        "mma.sync.aligned.m16n8k16.row.col.f16.f16.f16.f16 "
        "{%0,%1}, {%2,%3,%4,%5}, {%6,%7}, {%0,%1};"
        : "+r"(c[0]), "+r"(c[1])
        : "r"(a[0]), "r"(a[1]), "r"(a[2]), "r"(a[3]), "r"(b0), "r"(b1));
}

__device__ __forceinline__ uint32_t sw_off(int row, int ch) {
    return (uint32_t)row * 64u + (uint32_t)((ch ^ ((row >> 1) & 3)) << 4);
}

#define BK 32
#define STAGES 3

// ================= BIG tile GEMM: 256x128, warp tile 64x64 (for proj only) =================
#define BM2 256
#define BN2 128
#define ST2_BYTES 24576                 // 16KB A + 8KB B
#define GEMM2_SMEM (STAGES * ST2_BYTES) // 73728
#define A2_BYTES 16384

__global__ __launch_bounds__(256, 2) void hgemm_big(
    const __half* __restrict__ A, const __half* __restrict__ Bt, __half* __restrict__ C,
    int N, int K)
{
    extern __shared__ char smem[];
    const uint32_t sbase = smem_u32(smem);
    const int tid = threadIdx.x;
    const int wid = tid >> 5, lane = tid & 31;
    const int warp_m = wid & 3, warp_n = wid >> 2;      // 4 x 2
    const int m0 = blockIdx.y * BM2, n0 = blockIdx.x * BN2;

    const uint32_t offA[4] = { sw_off(tid, 0), sw_off(tid, 1), sw_off(tid, 2), sw_off(tid, 3) };
    const __half* Ag = A + (size_t)(m0 + tid) * K;
    const int blrow = tid >> 1;
    const int bc0 = (tid & 1) * 2;
    const uint32_t offB0 = sw_off(blrow, bc0);
    const uint32_t offB1 = sw_off(blrow, bc0 + 1);
    const bool bok = (n0 + blrow) < N;
    const int brow = bok ? (n0 + blrow) : (N - 1);
    const __half* Bg = Bt + (size_t)brow * K + bc0 * 8;
    const uint32_t bsz = bok ? 16u : 0u;

    const int nT = K / BK;

    #pragma unroll
    for (int s = 0; s < STAGES - 1; s++) {
        const int k0 = s * BK;
        uint32_t sb = sbase + s * ST2_BYTES;
        #pragma unroll
        for (int i = 0; i < 4; i++)
            cp_async16(sb + offA[i], Ag + k0 + i * 8, 16u);
        cp_async16(sb + A2_BYTES + offB0, Bg + k0, bsz);
        cp_async16(sb + A2_BYTES + offB1, Bg + k0 + 8, bsz);
        cp_commit();
    }

    const int mat = lane >> 3;
    const int lrow8 = (mat & 1) * 8 + (lane & 7);
    const int lch = mat >> 1;

    uint32_t acc[4][8][2];
    #pragma unroll
    for (int i = 0; i < 4; i++)
        #pragma unroll
        for (int j = 0; j < 8; j++) { acc[i][j][0] = 0u; acc[i][j][1] = 0u; }

    for (int kt = 0; kt < nT; kt++) {
        cp_wait<STAGES - 2>();
        __syncthreads();
        const uint32_t sb = sbase + (kt % STAGES) * ST2_BYTES;

        #pragma unroll
        for (int kk = 0; kk < 2; kk++) {
            const int ch = kk * 2 + lch;
            uint32_t af[4][4];
            #pragma unroll
            for (int mt = 0; mt < 4; mt++) {
                int r = warp_m * 64 + mt * 16 + lrow8;
                ldmatrix_x4(af[mt], sb + sw_off(r, ch));
            }
            uint32_t bf[4][4];
            #pragma unroll
            for (int nt = 0; nt < 4; nt++) {
                int r = warp_n * 64 + nt * 16 + lrow8;
                ldmatrix_x4(bf[nt], sb + A2_BYTES + sw_off(r, ch));
            }
            #pragma unroll
            for (int mt = 0; mt < 4; mt++)
                #pragma unroll
                for (int n8 = 0; n8 < 8; n8++) {
                    int nt = n8 >> 1, sel = n8 & 1;
                    mma16816h(acc[mt][n8], af[mt], bf[nt][sel], bf[nt][sel + 2]);
                }
        }

        const int nk = kt + STAGES - 1;
        if (nk < nT) {
            const int k0 = nk * BK;
            uint32_t sw = sbase + (nk % STAGES) * ST2_BYTES;
            #pragma unroll
            for (int i = 0; i < 4; i++)
                cp_async16(sw + offA[i], Ag + k0 + i * 8, 16u);
            cp_async16(sw + A2_BYTES + offB0, Bg + k0, bsz);
            cp_async16(sw + A2_BYTES + offB1, Bg + k0 + 8, bsz);
        }
        cp_commit();
    }

    const int gq = lane >> 2, t4 = lane & 3;
    #pragma unroll
    for (int mt = 0; mt < 4; mt++) {
        #pragma unroll
        for (int n8 = 0; n8 < 8; n8++) {
            int col = n0 + warp_n * 64 + n8 * 8 + t4 * 2;
            if (col >= N) continue;
            int row0 = m0 + warp_m * 64 + mt * 16 + gq;
            #pragma unroll
            for (int h = 0; h < 2; h++) {
                int r = row0 + h * 8;
                *(__half2*)(C + (size_t)r * N + col) = *(__half2*)&acc[mt][n8][h];
            }
        }
    }
}

// ================= 128x128 GEMM (round-8 proven), warp tile 64x32 =================
#define STAGE_BYTES 16384
#define GEMM_SMEM (STAGES * STAGE_BYTES)

// EPI: 0 = half plain, 1 = float resid + ls*acc, 2 = half 10*tanh(acc/10)
template <int EPI>
__global__ __launch_bounds__(256, 3) void hgemm(
    const __half* __restrict__ A, const __half* __restrict__ Bt, void* __restrict__ Cv,
    int N, int K, const float* __restrict__ resid, const float* __restrict__ ls)
{
    extern __shared__ char smem[];
    const uint32_t sbase = smem_u32(smem);
    const int tid = threadIdx.x;
    const int wid = tid >> 5, lane = tid & 31;
    const int warp_m = wid & 1, warp_n = wid >> 1;
    const int m0 = blockIdx.y * 128, n0 = blockIdx.x * 128;

    const int lrow = tid >> 1;
    const int c0 = (tid & 1) * 2;
    const uint32_t offA0 = sw_off(lrow, c0);
    const uint32_t offA1 = sw_off(lrow, c0 + 1);
    const __half* Ag = A + (size_t)(m0 + lrow) * K + c0 * 8;
    const bool bok = (n0 + lrow) < N;
    const int brow = bok ? (n0 + lrow) : (N - 1);
    const __half* Bg = Bt + (size_t)brow * K + c0 * 8;
    const uint32_t bsz = bok ? 16u : 0u;

    const int nT = K / BK;

    #pragma unroll
    for (int s = 0; s < STAGES - 1; s++) {
        const int k0 = s * BK;
        uint32_t sb = sbase + s * STAGE_BYTES;
        cp_async16(sb + offA0, Ag + k0, 16u);
        cp_async16(sb + offA1, Ag + k0 + 8, 16u);
        cp_async16(sb + 8192 + offA0, Bg + k0, bsz);
        cp_async16(sb + 8192 + offA1, Bg + k0 + 8, bsz);
        cp_commit();
    }

    const int mat = lane >> 3;
    const int lrow8 = (mat & 1) * 8 + (lane & 7);
    const int lch = mat >> 1;

    uint32_t acc[4][4][2];
    #pragma unroll
    for (int i = 0; i < 4; i++)
        #pragma unroll
        for (int j = 0; j < 4; j++) { acc[i][j][0] = 0u; acc[i][j][1] = 0u; }

    for (int kt = 0; kt < nT; kt++) {
        cp_wait<STAGES - 2>();
        __syncthreads();
        const uint32_t sb = sbase + (kt % STAGES) * STAGE_BYTES;

        #pragma unroll
        for (int kk = 0; kk < 2; kk++) {
            uint32_t af[4][4];
            #pragma unroll
            for (int mt = 0; mt < 4; mt++) {
                int r = warp_m * 64 + mt * 16 + lrow8;
                ldmatrix_x4(af[mt], sb + sw_off(r, kk * 2 + lch));
            }
            uint32_t bf[2][4];
            #pragma unroll
            for (int nt = 0; nt < 2; nt++) {
                int r = warp_n * 32 + nt * 16 + lrow8;
                ldmatrix_x4(bf[nt], sb + 8192 + sw_off(r, kk * 2 + lch));
            }
            #pragma unroll
            for (int mt = 0; mt < 4; mt++)
                #pragma unroll
                for (int n8 = 0; n8 < 4; n8++) {
                    int nt = n8 >> 1, sel = n8 & 1;
                    mma16816h(acc[mt][n8], af[mt], bf[nt][sel], bf[nt][sel + 2]);
                }
        }

        const int nk = kt + STAGES - 1;
        if (nk < nT) {
            const int k0 = nk * BK;
            uint32_t sw = sbase + (nk % STAGES) * STAGE_BYTES;
            cp_async16(sw + offA0, Ag + k0, 16u);
            cp_async16(sw + offA1, Ag + k0 + 8, 16u);
            cp_async16(sw + 8192 + offA0, Bg + k0, bsz);
            cp_async16(sw + 8192 + offA1, Bg + k0 + 8, bsz);
        }
        cp_commit();
    }

    const int gq = lane >> 2, t4 = lane & 3;
    #pragma unroll
    for (int mt = 0; mt < 4; mt++) {
        #pragma unroll
        for (int n8 = 0; n8 < 4; n8++) {
            int col = n0 + warp_n * 32 + n8 * 8 + t4 * 2;
            if (col >= N) continue;
            int row0 = m0 + warp_m * 64 + mt * 16 + gq;
            #pragma unroll
            for (int h = 0; h < 2; h++) {
                int r = row0 + h * 8;
                __half2 hv = *(__half2*)&acc[mt][n8][h];
                if (EPI == 0) {
                    *(__half2*)((__half*)Cv + (size_t)r * N + col) = hv;
                } else if (EPI == 1) {
                    float2 v = __half22float2(hv);
                    float2 rv = *(const float2*)(resid + (size_t)r * N + col);
                    float2 lv = *(const float2*)(ls + col);
                    float2 o;
                    o.x = rv.x + lv.x * v.x;
                    o.y = rv.y + lv.y * v.y;
                    *(float2*)((float*)Cv + (size_t)r * N + col) = o;
                } else {
                    float2 v = __half22float2(hv);
                    v.x = 10.f * tanhf(v.x * 0.1f);
                    v.y = 10.f * tanhf(v.y * 0.1f);
                    *(__half2*)((__half*)Cv + (size_t)r * N + col) = __floats2half2_rn(v.x, v.y);
                }
            }
        }
    }
}

// ---------------- Grouped-MoE gather GEMM (128x128 tiles) ----------------
__global__ __launch_bounds__(256, 3) void hgemm_moe()
{
    const int tileIdx = blockIdx.y;
    if (tileIdx >= g_ntiles) return;

    extern __shared__ char smem[];
    const uint32_t sbase = smem_u32(smem);
    const int tid = threadIdx.x;
    const int wid = tid >> 5, lane = tid & 31;
    const int warp_m = wid & 1, warp_n = wid >> 1;
    const int m0 = tileIdx * 128, n0 = blockIdx.x * 128;

    const int e = g_tileexp[tileIdx];
    const int offE = g_off[e], cntE = g_cnt[e];
    const __half* Bbase = g_GtE + (size_t)e * R2 * R3;

    const int lrow = tid >> 1;
    const int c0 = (tid & 1) * 2;
    const uint32_t offA0 = sw_off(lrow, c0);
    const uint32_t offA1 = sw_off(lrow, c0 + 1);
    const bool avalid = (m0 + lrow - offE) < cntE;
    const int tok = avalid ? g_rowtok[m0 + lrow] : 0;
    const __half* Ag = g_lat + (size_t)tok * R3 + c0 * 8;
    const __half* Bg = Bbase + (size_t)(n0 + lrow) * R3 + c0 * 8;

    const int nT = R3 / BK;

    #pragma unroll
    for (int s = 0; s < STAGES - 1; s++) {
        const int k0 = s * BK;
        uint32_t sb = sbase + s * STAGE_BYTES;
        cp_async16(sb + offA0, Ag + k0, 16u);
        cp_async16(sb + offA1, Ag + k0 + 8, 16u);
        cp_async16(sb + 8192 + offA0, Bg + k0, 16u);
        cp_async16(sb + 8192 + offA1, Bg + k0 + 8, 16u);
        cp_commit();
    }

    const int mat = lane >> 3;
    const int lrow8 = (mat & 1) * 8 + (lane & 7);
    const int lch = mat >> 1;

    uint32_t acc[4][4][2];
    #pragma unroll
    for (int i = 0; i < 4; i++)
        #pragma unroll
        for (int j = 0; j < 4; j++) { acc[i][j][0] = 0u; acc[i][j][1] = 0u; }

    for (int kt = 0; kt < nT; kt++) {
        cp_wait<STAGES - 2>();
        __syncthreads();
        const uint32_t sb = sbase + (kt % STAGES) * STAGE_BYTES;

        #pragma unroll
        for (int kk = 0; kk < 2; kk++) {
            uint32_t af[4][4];
            #pragma unroll
            for (int mt = 0; mt < 4; mt++) {
                int r = warp_m * 64 + mt * 16 + lrow8;
                ldmatrix_x4(af[mt], sb + sw_off(r, kk * 2 + lch));
            }
            uint32_t bf[2][4];
            #pragma unroll
            for (int nt = 0; nt < 2; nt++) {
                int r = warp_n * 32 + nt * 16 + lrow8;
                ldmatrix_x4(bf[nt], sb + 8192 + sw_off(r, kk * 2 + lch));
            }
            #pragma unroll
            for (int mt = 0; mt < 4; mt++)
                #pragma unroll
                for (int n8 = 0; n8 < 4; n8++) {
                    int nt = n8 >> 1, sel = n8 & 1;
                    mma16816h(acc[mt][n8], af[mt], bf[nt][sel], bf[nt][sel + 2]);
                }
        }

        const int nk = kt + STAGES - 1;
        if (nk < nT) {
            const int k0 = nk * BK;
            uint32_t sw = sbase + (nk % STAGES) * STAGE_BYTES;
            cp_async16(sw + offA0, Ag + k0, 16u);
            cp_async16(sw + offA1, Ag + k0 + 8, 16u);
            cp_async16(sw + 8192 + offA0, Bg + k0, 16u);
            cp_async16(sw + 8192 + offA1, Bg + k0 + 8, 16u);
        }
        cp_commit();
    }

    const int gq = lane >> 2, t4 = lane & 3;
    #pragma unroll
    for (int mt = 0; mt < 4; mt++) {
        int row0 = m0 + warp_m * 64 + mt * 16 + gq;
        float pr[2];
        bool pv[2];
        #pragma unroll
        for (int h = 0; h < 2; h++) {
            int ri = row0 + h * 8;
            pv[h] = (ri - offE) < cntE;
            pr[h] = pv[h] ? g_rowp[ri] : 0.f;
        }
        #pragma unroll
        for (int n8 = 0; n8 < 4; n8++) {
            int col = n0 + warp_n * 32 + n8 * 8 + t4 * 2;
            #pragma unroll
            for (int h = 0; h < 2; h++) {
                if (!pv[h]) continue;
                int ri = row0 + h * 8;
                float2 v = __half22float2(*(__half2*)&acc[mt][n8][h]);
                *(__half2*)(g_easgn + (size_t)ri * R2 + col) =
                    __floats2half2_rn(pr[h] * v.x, pr[h] * v.y);
            }
        }
    }
}

// ---------------- weight transpose + fp16 cast ----------------
__global__ void transpose_cast(const float* __restrict__ in, __half* __restrict__ out,
                               int K, int N)
{
    __shared__ float t[32][33];
    int n0 = blockIdx.x * 32, k0 = blockIdx.y * 32;
    int tx = threadIdx.x, ty = threadIdx.y;
    #pragma unroll
    for (int i = 0; i < 4; i++) {
        int k = k0 + ty + 8 * i, n = n0 + tx;
        t[ty + 8 * i][tx] = (n < N && k < K) ? in[(size_t)k * N + n] : 0.f;
    }
    __syncthreads();
    #pragma unroll
    for (int i = 0; i < 4; i++) {
        int n = n0 + ty + 8 * i, k = k0 + tx;
        if (n < N && k < K) out[(size_t)n * K + k] = __float2half(t[tx][ty + 8 * i]);
    }
}

// batched per-expert transpose of G: [E][R3][R2] -> [E][R2][R3]
__global__ void transpose_cast_G(const float* __restrict__ in, __half* __restrict__ out)
{
    __shared__ float t[32][33];
    int e = blockIdx.z;
    const float* ge = in + (size_t)e * R3 * R2;
    __half* oe = out + (size_t)e * R2 * R3;
    int n0 = blockIdx.x * 32, k0 = blockIdx.y * 32;
    int tx = threadIdx.x, ty = threadIdx.y;
    #pragma unroll
    for (int i = 0; i < 4; i++) {
        int k = k0 + ty + 8 * i, n = n0 + tx;
        t[ty + 8 * i][tx] = ge[(size_t)k * R2 + n];
    }
    __syncthreads();
    #pragma unroll
    for (int i = 0; i < 4; i++) {
        int n = n0 + ty + 8 * i, k = k0 + tx;
        oe[(size_t)n * R3 + k] = __float2half(t[tx][ty + 8 * i]);
    }
}

// ---------------- RMSNorm ----------------
__global__ __launch_bounds__(256) void rmsnorm_kernel(
    const float* __restrict__ x, const float* __restrict__ w, __half* __restrict__ out)
{
    int t = blockIdx.x;
    const float* xr = x + (size_t)t * DMODEL;
    int tid = threadIdx.x;
    float v0 = xr[tid], v1 = xr[tid + 256], v2 = xr[tid + 512];
    float s = v0 * v0 + v1 * v1 + v2 * v2;
    #pragma unroll
    for (int o = 16; o; o >>= 1) s += __shfl_xor_sync(0xffffffffu, s, o);
    __shared__ float red[8];
    __shared__ float scale;
    int wid = tid >> 5, lane = tid & 31;
    if (lane == 0) red[wid] = s;
    __syncthreads();
    if (tid < 32) {
        float r = (tid < 8) ? red[tid] : 0.f;
        #pragma unroll
        for (int o = 4; o; o >>= 1) r += __shfl_xor_sync(0xffffffffu, r, o);
        if (tid == 0) scale = rsqrtf(r / (float)DMODEL + 1e-5f);
    }
    __syncthreads();
    float sc = scale;
    __half* orow = out + (size_t)t * DMODEL;
    orow[tid]       = __float2half(v0 * sc * w[tid]);
    orow[tid + 256] = __float2half(v1 * sc * w[tid + 256]);
    orow[tid + 512] = __float2half(v2 * sc * w[tid + 512]);
}

// ---------------- Chunked selective scan ----------------
__global__ __launch_bounds__(64) void scan_pass1(
    const __half* __restrict__ proj, const float* __restrict__ dt_bias)
{
    int c = blockIdx.x, bh = blockIdx.y;
    int b = bh / NHEADS, h = bh % NHEADS;
    int d = threadIdx.x;
    float bias = dt_bias[h];
    const __half* base = proj + (size_t)(b * SEQ + c * CHUNK) * KPROJ;
    float Aacc = 1.f, hl = 0.f;
    #pragma unroll 4
    for (int t = 0; t < CHUNK; t++) {
        float dt = __half2float(base[(size_t)t * KPROJ + 2 * DINNER + h]);
        float u  = __half2float(base[(size_t)t * KPROJ + h * DHEAD + d]);
        float alpha = 1.f / (1.f + __expf(dt + bias));
        hl = fmaf(alpha, hl, u);
        Aacc *= alpha;
    }
    int idx = bh * NCHUNK + c;
    if (d == 0) g_cA[idx] = Aacc;
    g_cB[(size_t)idx * DHEAD + d] = hl;
}

__global__ __launch_bounds__(64) void scan_pass2()
{
    int bh = blockIdx.x;
    int d = threadIdx.x;
    float hc = 0.f;
    #pragma unroll
    for (int c = 0; c < NCHUNK; c++) {
        int idx = bh * NCHUNK + c;
        g_carry[(size_t)idx * DHEAD + d] = hc;
        hc = fmaf(g_cA[idx], hc, g_cB[(size_t)idx * DHEAD + d]);
    }
}

__global__ __launch_bounds__(64) void scan_pass3(
    const __half* __restrict__ proj, const float* __restrict__ dt_bias,
    __half* __restrict__ y)
{
    int c = blockIdx.x, bh = blockIdx.y;
    int b = bh / NHEADS, h = bh % NHEADS;
    int d = threadIdx.x;
    float bias = dt_bias[h];
    const __half* base = proj + (size_t)(b * SEQ + c * CHUNK) * KPROJ;
    __half* yb = y + (size_t)(b * SEQ + c * CHUNK) * DINNER + h * DHEAD + d;
    float hl = g_carry[((size_t)bh * NCHUNK + c) * DHEAD + d];
    #pragma unroll 4
    for (int t = 0; t < CHUNK; t++) {
        float dt = __half2float(base[(size_t)t * KPROJ + 2 * DINNER + h]);
        float u  = __half2float(base[(size_t)t * KPROJ + h * DHEAD + d]);
        float z  = __half2float(base[(size_t)t * KPROJ + DINNER + h * DHEAD + d]);
        float alpha = 1.f / (1.f + __expf(dt + bias));
        hl = fmaf(alpha, hl, u);
        float sig = 1.f / (1.f + __expf(-z));
        float v = hl * z * sig;
        yb[(size_t)t * DINNER] = __float2half(10.f * tanhf(v * 0.1f));
    }
}

// ---------------- Router ----------------
__global__ __launch_bounds__(256) void router_kernel(
    const __half* __restrict__ x2n, const float* __restrict__ Wr)
{
    int t = blockIdx.x;
    int wid = threadIdx.x >> 5, lane = threadIdx.x & 31;
    const __half* xr = x2n + (size_t)t * DMODEL;
    float s = 0.f;
    for (int r = lane; r < DMODEL; r += 32)
        s = fmaf(__half2float(xr[r]), Wr[r * NEXP + wid], s);
    #pragma unroll
    for (int o = 16; o; o >>= 1) s += __shfl_xor_sync(0xffffffffu, s, o);
    __shared__ float logits[NEXP];
    if (lane == 0) logits[wid] = s * 2.0f;
    __syncthreads();
    if (threadIdx.x == 0) {
        float best = -1e30f; int bi = 0;
        #pragma unroll
        for (int e = 0; e < NEXP; e++)
            if (logits[e] > best) { best = logits[e]; bi = e; }
        float sec = -1e30f; int si = 0;
        #pragma unroll
        for (int e = 0; e < NEXP; e++)
            if (e != bi && logits[e] > sec) { sec = logits[e]; si = e; }
        float p0 = 1.f / (1.f + __expf(sec - best));
        float p1 = 1.f - p0;
        g_e01[t] = bi | (si << 8);
        g_p01[t] = make_float2(p0, p1);
        atomicAdd(&g_cnt[bi], 1);
        atomicAdd(&g_cnt[si], 1);
    }
}

__global__ void moe_zero()
{
    if (threadIdx.x < NEXP) g_cnt[threadIdx.x] = 0;
}

__global__ void moe_offsets()
{
    if (threadIdx.x == 0) {
        int acc = 0;
        for (int e = 0; e < NEXP; e++) {
            g_off[e] = acc;
            g_cur[e] = acc;
            int tiles = (g_cnt[e] + 127) / 128;
            for (int i = 0; i < tiles; i++) g_tileexp[acc / 128 + i] = e;
            acc += tiles * 128;
        }
        g_off[NEXP] = acc;
        g_ntiles = acc / 128;
    }
}

__global__ __launch_bounds__(256) void moe_assign()
{
    int t = blockIdx.x * 256 + threadIdx.x;
    if (t >= NTOK) return;
    int ee = g_e01[t];
    int e0 = ee & 0xff, e1 = (ee >> 8) & 0xff;
    float2 p = g_p01[t];
    int pos0 = atomicAdd(&g_cur[e0], 1);
    g_rowtok[pos0] = t; g_rowp[pos0] = p.x; g_slot[2 * t] = pos0;
    int pos1 = atomicAdd(&g_cur[e1], 1);
    g_rowtok[pos1] = t; g_rowp[pos1] = p.y; g_slot[2 * t + 1] = pos1;
}

__global__ __launch_bounds__(256) void moe_combine()
{
    int t = blockIdx.x;
    int s0 = g_slot[2 * t], s1 = g_slot[2 * t + 1];
    const __half2* r0 = (const __half2*)(g_easgn + (size_t)s0 * R2);
    const __half2* r1 = (const __half2*)(g_easgn + (size_t)s1 * R2);
    __half2* o = (__half2*)(g_moe + (size_t)t * R2);
    int i = threadIdx.x;
    #pragma unroll
    for (int j = 0; j < 2; j++) {
        int k = i + j * 256;
        float2 a = __half22float2(r0[k]);
        float2 b = __half22float2(r1[k]);
        o[k] = __floats2half2_rn(a.x + b.x, a.y + b.y);
    }
}

// ---------------- Host launcher ----------------
extern "C" void kernel_launch(void* const* d_in, const int* in_sizes, int n_in,
                              void* d_out, int out_size)
{
    const float* x        = (const float*)d_in[0];
    const float* rms1_w   = (const float*)d_in[1];
    const float* W_in     = (const float*)d_in[2];
    const float* dt_bias  = (const float*)d_in[3];
    const float* W_out    = (const float*)d_in[4];
    const float* ls1      = (const float*)d_in[5];
    const float* rms2_w   = (const float*)d_in[6];
    const float* W_down   = (const float*)d_in[7];
    const float* W_router = (const float*)d_in[8];
    const float* G        = (const float*)d_in[9];
    const float* W_up     = (const float*)d_in[10];
    const float* ls2      = (const float*)d_in[11];
    float* out = (float*)d_out;

    __half *xn, *proj, *y, *x2n, *lat, *moe;
    __half *WinT, *WoutT, *WdownT, *GtE, *WupT;
    float *x1;
    cudaGetSymbolAddress((void**)&xn,     g_xn);
    cudaGetSymbolAddress((void**)&proj,   g_proj);
    cudaGetSymbolAddress((void**)&y,      g_y);
    cudaGetSymbolAddress((void**)&x1,     g_x1);
    cudaGetSymbolAddress((void**)&x2n,    g_x2n);
    cudaGetSymbolAddress((void**)&lat,    g_lat);
    cudaGetSymbolAddress((void**)&moe,    g_moe);
    cudaGetSymbolAddress((void**)&WinT,   g_WinT);
    cudaGetSymbolAddress((void**)&WoutT,  g_WoutT);
    cudaGetSymbolAddress((void**)&WdownT, g_WdownT);
    cudaGetSymbolAddress((void**)&GtE,    g_GtE);
    cudaGetSymbolAddress((void**)&WupT,   g_WupT);

    cudaFuncSetAttribute(hgemm_big, cudaFuncAttributeMaxDynamicSharedMemorySize, GEMM2_SMEM);
    cudaFuncSetAttribute(hgemm<0>, cudaFuncAttributeMaxDynamicSharedMemorySize, GEMM_SMEM);
    cudaFuncSetAttribute(hgemm<1>, cudaFuncAttributeMaxDynamicSharedMemorySize, GEMM_SMEM);
    cudaFuncSetAttribute(hgemm<2>, cudaFuncAttributeMaxDynamicSharedMemorySize, GEMM_SMEM);
    cudaFuncSetAttribute(hgemm_moe, cudaFuncAttributeMaxDynamicSharedMemorySize, GEMM_SMEM);

    dim3 tb(32, 8);
    transpose_cast<<<dim3((KPROJ + 31) / 32, DMODEL / 32), tb>>>(W_in, WinT, DMODEL, KPROJ);
    rmsnorm_kernel<<<NTOK, 256>>>(x, rms1_w, xn);
    transpose_cast<<<dim3(DMODEL / 32, DINNER / 32), tb>>>(W_out, WoutT, DINNER, DMODEL);
    // proj = xn @ W_in  [8192, 6192]  -- big 256x128 tiles
    hgemm_big<<<dim3((KPROJ + BN2 - 1) / BN2, NTOK / BM2), 256, GEMM2_SMEM>>>(
        xn, WinT, proj, KPROJ, DMODEL);
    transpose_cast<<<dim3(R3 / 32, DMODEL / 32), tb>>>(W_down, WdownT, DMODEL, R3);
    transpose_cast<<<dim3(DMODEL / 32, R2 / 32), tb>>>(W_up, WupT, R2, DMODEL);
    transpose_cast_G<<<dim3(R2 / 32, R3 / 32, NEXP), tb>>>(G, GtE);

    scan_pass1<<<dim3(NCHUNK, BATCH * NHEADS), 64>>>(proj, dt_bias);
    scan_pass2<<<BATCH * NHEADS, 64>>>();
    scan_pass3<<<dim3(NCHUNK, BATCH * NHEADS), 64>>>(proj, dt_bias, y);
    // x1 = x + ls1 * (y @ W_out)  -- 128x128 tiles (384 CTAs)
    hgemm<1><<<dim3(DMODEL / 128, NTOK / 128), 256, GEMM_SMEM>>>(
        y, WoutT, x1, DMODEL, DINNER, x, ls1);
    rmsnorm_kernel<<<NTOK, 256>>>(x1, rms2_w, x2n);
    // lat = scaled_tanh(x2n @ W_down)  -- 128x128 tiles (128 CTAs)
    hgemm<2><<<dim3(R3 / 128, NTOK / 128), 256, GEMM_SMEM>>>(
        x2n, WdownT, lat, R3, DMODEL, nullptr, nullptr);
    moe_zero<<<1, 32>>>();
    router_kernel<<<NTOK, 256>>>(x2n, W_router);
    moe_offsets<<<1, 32>>>();
    moe_assign<<<(NTOK + 255) / 256, 256>>>();
    hgemm_moe<<<dim3(R2 / 128, MAXTILES), 256, GEMM_SMEM>>>();
    moe_combine<<<NTOK, 256>>>();
    // out = x1 + ls2 * (moe @ W_up)  -- 128x128 tiles (384 CTAs)
    hgemm<1><<<dim3(DMODEL / 128, NTOK / 128), 256, GEMM_SMEM>>>(
        moe, WupT, out, DMODEL, R2, x1, ls2);
}

// round 12
// speedup vs baseline: 1.2739x; 1.1124x over previous
#include <cuda_runtime.h>
#include <cuda_fp16.h>
#include <cstdint>
#include <math.h>

// ---------------- Problem constants ----------------
#define BATCH   2
#define SEQ     4096
#define NTOK    (BATCH * SEQ)      // 8192
#define DMODEL  768
#define DINNER  3072
#define NHEADS  48
#define DHEAD   64
#define NEXP    8
#define R3      256
#define R2      1024
#define KPROJ   (2 * DINNER + NHEADS)   // 6192
#define CHUNK   128
#define NCHUNK  (SEQ / CHUNK)           // 32
#define MAXROWS (NTOK * 2 + NEXP * 128) // 17408
#define MAXTILES (MAXROWS / 128)        // 136

// ---------------- Scratch (static device globals) ----------------
__device__ __half g_xn   [NTOK * DMODEL];
__device__ __half g_proj [NTOK * KPROJ];
__device__ __half g_y    [NTOK * DINNER];
__device__ float  g_x1   [NTOK * DMODEL];
__device__ __half g_x2n  [NTOK * DMODEL];
__device__ __half g_lat  [NTOK * R3];
__device__ __half g_moe  [NTOK * R2];
__device__ __half g_WinT  [KPROJ * DMODEL];
__device__ __half g_WoutT [DMODEL * DINNER];
__device__ __half g_WdownT[R3 * DMODEL];
__device__ __half g_GtE   [NEXP * R2 * R3];
__device__ __half g_WupT  [DMODEL * R2];
__device__ float g_cA   [BATCH * NHEADS * NCHUNK];
__device__ float g_cB   [BATCH * NHEADS * NCHUNK * DHEAD];
__device__ float g_carry[BATCH * NHEADS * NCHUNK * DHEAD];
__device__ int    g_cnt[NEXP];
__device__ int    g_off[NEXP + 1];
__device__ int    g_cur[NEXP];
__device__ int    g_tileexp[MAXTILES];
__device__ int    g_ntiles;
__device__ int    g_e01 [NTOK];
__device__ float2 g_p01 [NTOK];
__device__ int    g_rowtok[MAXROWS];
__device__ float  g_rowp [MAXROWS];
__device__ int    g_slot[NTOK * 2];
__device__ __half g_easgn[MAXROWS * R2];

// ---------------- small helpers ----------------
__device__ __forceinline__ uint32_t smem_u32(const void* p) {
    uint32_t a;
    asm("{ .reg .u64 t; cvta.to.shared.u64 t, %1; cvt.u32.u64 %0, t; }"
        : "=r"(a) : "l"(p));
    return a;
}
__device__ __forceinline__ void cp_async16(uint32_t saddr, const void* gaddr, uint32_t srcsize) {
    asm volatile("cp.async.cg.shared.global [%0], [%1], 16, %2;"
                 :: "r"(saddr), "l"(gaddr), "r"(srcsize) : "memory");
}
__device__ __forceinline__ void cp_commit() {
    asm volatile("cp.async.commit_group;" ::: "memory");
}
template <int N>
__device__ __forceinline__ void cp_wait() {
    asm volatile("cp.async.wait_group %0;" :: "n"(N) : "memory");
}
__device__ __forceinline__ void ldmatrix_x4(uint32_t* r, uint32_t addr) {
    asm volatile("ldmatrix.sync.aligned.m8n8.x4.shared.b16 {%0,%1,%2,%3}, [%4];"
                 : "=r"(r[0]), "=r"(r[1]), "=r"(r[2]), "=r"(r[3]) : "r"(addr));
}
__device__ __forceinline__ void mma16816h(uint32_t* c, const uint32_t* a, uint32_t b0, uint32_t b1) {
    asm volatile(
        "mma.sync.aligned.m16n8k16.row.col.f16.f16.f16.f16 "
        "{%0,%1}, {%2,%3,%4,%5}, {%6,%7}, {%0,%1};"
        : "+r"(c[0]), "+r"(c[1])
        : "r"(a[0]), "r"(a[1]), "r"(a[2]), "r"(a[3]), "r"(b0), "r"(b1));
}

__device__ __forceinline__ uint32_t sw_off(int row, int ch) {
    return (uint32_t)row * 64u + (uint32_t)((ch ^ ((row >> 1) & 3)) << 4);
}

#define BK 32
#define STAGES 4
#define STAGE_BYTES 16384
#define GEMM_SMEM (STAGES * STAGE_BYTES)   // 65536

// ================= 128x128 GEMM, warp tile 64x32, 4-stage cp.async =================
// EPI: 0 = half plain, 1 = float resid + ls*acc, 2 = half 10*tanh(acc/10)
template <int EPI>
__global__ __launch_bounds__(256, 3) void hgemm(
    const __half* __restrict__ A, const __half* __restrict__ Bt, void* __restrict__ Cv,
    int N, int K, const float* __restrict__ resid, const float* __restrict__ ls)
{
    extern __shared__ char smem[];
    const uint32_t sbase = smem_u32(smem);
    const int tid = threadIdx.x;
    const int wid = tid >> 5, lane = tid & 31;
    const int warp_m = wid & 1, warp_n = wid >> 1;
    const int m0 = blockIdx.y * 128, n0 = blockIdx.x * 128;

    const int lrow = tid >> 1;
    const int c0 = (tid & 1) * 2;
    const uint32_t offA0 = sw_off(lrow, c0);
    const uint32_t offA1 = sw_off(lrow, c0 + 1);
    const __half* Ag = A + (size_t)(m0 + lrow) * K + c0 * 8;
    const bool bok = (n0 + lrow) < N;
    const int brow = bok ? (n0 + lrow) : (N - 1);
    const __half* Bg = Bt + (size_t)brow * K + c0 * 8;
    const uint32_t bsz = bok ? 16u : 0u;

    const int nT = K / BK;

    #pragma unroll
    for (int s = 0; s < STAGES - 1; s++) {
        const int k0 = s * BK;
        uint32_t sb = sbase + s * STAGE_BYTES;
        cp_async16(sb + offA0, Ag + k0, 16u);
        cp_async16(sb + offA1, Ag + k0 + 8, 16u);
        cp_async16(sb + 8192 + offA0, Bg + k0, bsz);
        cp_async16(sb + 8192 + offA1, Bg + k0 + 8, bsz);
        cp_commit();
    }

    const int mat = lane >> 3;
    const int lrow8 = (mat & 1) * 8 + (lane & 7);
    const int lch = mat >> 1;

    uint32_t acc[4][4][2];
    #pragma unroll
    for (int i = 0; i < 4; i++)
        #pragma unroll
        for (int j = 0; j < 4; j++) { acc[i][j][0] = 0u; acc[i][j][1] = 0u; }

    for (int kt = 0; kt < nT; kt++) {
        cp_wait<STAGES - 2>();
        __syncthreads();
        const uint32_t sb = sbase + (kt % STAGES) * STAGE_BYTES;

        #pragma unroll
        for (int kk = 0; kk < 2; kk++) {
            uint32_t af[4][4];
            #pragma unroll
            for (int mt = 0; mt < 4; mt++) {
                int r = warp_m * 64 + mt * 16 + lrow8;
                ldmatrix_x4(af[mt], sb + sw_off(r, kk * 2 + lch));
            }
            uint32_t bf[2][4];
            #pragma unroll
            for (int nt = 0; nt < 2; nt++) {
                int r = warp_n * 32 + nt * 16 + lrow8;
                ldmatrix_x4(bf[nt], sb + 8192 + sw_off(r, kk * 2 + lch));
            }
            #pragma unroll
            for (int mt = 0; mt < 4; mt++)
                #pragma unroll
                for (int n8 = 0; n8 < 4; n8++) {
                    int nt = n8 >> 1, sel = n8 & 1;
                    mma16816h(acc[mt][n8], af[mt], bf[nt][sel], bf[nt][sel + 2]);
                }
        }

        const int nk = kt + STAGES - 1;
        if (nk < nT) {
            const int k0 = nk * BK;
            uint32_t sw = sbase + (nk % STAGES) * STAGE_BYTES;
            cp_async16(sw + offA0, Ag + k0, 16u);
            cp_async16(sw + offA1, Ag + k0 + 8, 16u);
            cp_async16(sw + 8192 + offA0, Bg + k0, bsz);
            cp_async16(sw + 8192 + offA1, Bg + k0 + 8, bsz);
        }
        cp_commit();
    }

    const int gq = lane >> 2, t4 = lane & 3;
    #pragma unroll
    for (int mt = 0; mt < 4; mt++) {
        #pragma unroll
        for (int n8 = 0; n8 < 4; n8++) {
            int col = n0 + warp_n * 32 + n8 * 8 + t4 * 2;
            if (col >= N) continue;
            int row0 = m0 + warp_m * 64 + mt * 16 + gq;
            #pragma unroll
            for (int h = 0; h < 2; h++) {
                int r = row0 + h * 8;
                __half2 hv = *(__half2*)&acc[mt][n8][h];
                if (EPI == 0) {
                    *(__half2*)((__half*)Cv + (size_t)r * N + col) = hv;
                } else if (EPI == 1) {
                    float2 v = __half22float2(hv);
                    float2 rv = *(const float2*)(resid + (size_t)r * N + col);
                    float2 lv = *(const float2*)(ls + col);
                    float2 o;
                    o.x = rv.x + lv.x * v.x;
                    o.y = rv.y + lv.y * v.y;
                    *(float2*)((float*)Cv + (size_t)r * N + col) = o;
                } else {
                    float2 v = __half22float2(hv);
                    v.x = 10.f * tanhf(v.x * 0.1f);
                    v.y = 10.f * tanhf(v.y * 0.1f);
                    *(__half2*)((__half*)Cv + (size_t)r * N + col) = __floats2half2_rn(v.x, v.y);
                }
            }
        }
    }
}

// ---------------- Grouped-MoE gather GEMM (128x128 tiles) ----------------
__global__ __launch_bounds__(256, 3) void hgemm_moe()
{
    const int tileIdx = blockIdx.y;
    if (tileIdx >= g_ntiles) return;

    extern __shared__ char smem[];
    const uint32_t sbase = smem_u32(smem);
    const int tid = threadIdx.x;
    const int wid = tid >> 5, lane = tid & 31;
    const int warp_m = wid & 1, warp_n = wid >> 1;
    const int m0 = tileIdx * 128, n0 = blockIdx.x * 128;

    const int e = g_tileexp[tileIdx];
    const int offE = g_off[e], cntE = g_cnt[e];
    const __half* Bbase = g_GtE + (size_t)e * R2 * R3;

    const int lrow = tid >> 1;
    const int c0 = (tid & 1) * 2;
    const uint32_t offA0 = sw_off(lrow, c0);
    const uint32_t offA1 = sw_off(lrow, c0 + 1);
    const bool avalid = (m0 + lrow - offE) < cntE;
    const int tok = avalid ? g_rowtok[m0 + lrow] : 0;
    const __half* Ag = g_lat + (size_t)tok * R3 + c0 * 8;
    const __half* Bg = Bbase + (size_t)(n0 + lrow) * R3 + c0 * 8;

    const int nT = R3 / BK;   // 8

    #pragma unroll
    for (int s = 0; s < STAGES - 1; s++) {
        const int k0 = s * BK;
        uint32_t sb = sbase + s * STAGE_BYTES;
        cp_async16(sb + offA0, Ag + k0, 16u);
        cp_async16(sb + offA1, Ag + k0 + 8, 16u);
        cp_async16(sb + 8192 + offA0, Bg + k0, 16u);
        cp_async16(sb + 8192 + offA1, Bg + k0 + 8, 16u);
        cp_commit();
    }

    const int mat = lane >> 3;
    const int lrow8 = (mat & 1) * 8 + (lane & 7);
    const int lch = mat >> 1;

    uint32_t acc[4][4][2];
    #pragma unroll
    for (int i = 0; i < 4; i++)
        #pragma unroll
        for (int j = 0; j < 4; j++) { acc[i][j][0] = 0u; acc[i][j][1] = 0u; }

    for (int kt = 0; kt < nT; kt++) {
        cp_wait<STAGES - 2>();
        __syncthreads();
        const uint32_t sb = sbase + (kt % STAGES) * STAGE_BYTES;

        #pragma unroll
        for (int kk = 0; kk < 2; kk++) {
            uint32_t af[4][4];
            #pragma unroll
            for (int mt = 0; mt < 4; mt++) {
                int r = warp_m * 64 + mt * 16 + lrow8;
                ldmatrix_x4(af[mt], sb + sw_off(r, kk * 2 + lch));
            }
            uint32_t bf[2][4];
            #pragma unroll
            for (int nt = 0; nt < 2; nt++) {
                int r = warp_n * 32 + nt * 16 + lrow8;
                ldmatrix_x4(bf[nt], sb + 8192 + sw_off(r, kk * 2 + lch));
            }
            #pragma unroll
            for (int mt = 0; mt < 4; mt++)
                #pragma unroll
                for (int n8 = 0; n8 < 4; n8++) {
                    int nt = n8 >> 1, sel = n8 & 1;
                    mma16816h(acc[mt][n8], af[mt], bf[nt][sel], bf[nt][sel + 2]);
                }
        }

        const int nk = kt + STAGES - 1;
        if (nk < nT) {
            const int k0 = nk * BK;
            uint32_t sw = sbase + (nk % STAGES) * STAGE_BYTES;
            cp_async16(sw + offA0, Ag + k0, 16u);
            cp_async16(sw + offA1, Ag + k0 + 8, 16u);
            cp_async16(sw + 8192 + offA0, Bg + k0, 16u);
            cp_async16(sw + 8192 + offA1, Bg + k0 + 8, 16u);
        }
        cp_commit();
    }

    const int gq = lane >> 2, t4 = lane & 3;
    #pragma unroll
    for (int mt = 0; mt < 4; mt++) {
        int row0 = m0 + warp_m * 64 + mt * 16 + gq;
        float pr[2];
        bool pv[2];
        #pragma unroll
        for (int h = 0; h < 2; h++) {
            int ri = row0 + h * 8;
            pv[h] = (ri - offE) < cntE;
            pr[h] = pv[h] ? g_rowp[ri] : 0.f;
        }
        #pragma unroll
        for (int n8 = 0; n8 < 4; n8++) {
            int col = n0 + warp_n * 32 + n8 * 8 + t4 * 2;
            #pragma unroll
            for (int h = 0; h < 2; h++) {
                if (!pv[h]) continue;
                int ri = row0 + h * 8;
                float2 v = __half22float2(*(__half2*)&acc[mt][n8][h]);
                *(__half2*)(g_easgn + (size_t)ri * R2 + col) =
                    __floats2half2_rn(pr[h] * v.x, pr[h] * v.y);
            }
        }
    }
}

// ---------------- weight transpose + fp16 cast ----------------
__global__ void transpose_cast(const float* __restrict__ in, __half* __restrict__ out,
                               int K, int N)
{
    __shared__ float t[32][33];
    int n0 = blockIdx.x * 32, k0 = blockIdx.y * 32;
    int tx = threadIdx.x, ty = threadIdx.y;
    #pragma unroll
    for (int i = 0; i < 4; i++) {
        int k = k0 + ty + 8 * i, n = n0 + tx;
        t[ty + 8 * i][tx] = (n < N && k < K) ? in[(size_t)k * N + n] : 0.f;
    }
    __syncthreads();
    #pragma unroll
    for (int i = 0; i < 4; i++) {
        int n = n0 + ty + 8 * i, k = k0 + tx;
        if (n < N && k < K) out[(size_t)n * K + k] = __float2half(t[tx][ty + 8 * i]);
    }
}

// batched per-expert transpose of G: [E][R3][R2] -> [E][R2][R3]
__global__ void transpose_cast_G(const float* __restrict__ in, __half* __restrict__ out)
{
    __shared__ float t[32][33];
    int e = blockIdx.z;
    const float* ge = in + (size_t)e * R3 * R2;
    __half* oe = out + (size_t)e * R2 * R3;
    int n0 = blockIdx.x * 32, k0 = blockIdx.y * 32;
    int tx = threadIdx.x, ty = threadIdx.y;
    #pragma unroll
    for (int i = 0; i < 4; i++) {
        int k = k0 + ty + 8 * i, n = n0 + tx;
        t[ty + 8 * i][tx] = ge[(size_t)k * R2 + n];
    }
    __syncthreads();
    #pragma unroll
    for (int i = 0; i < 4; i++) {
        int n = n0 + ty + 8 * i, k = k0 + tx;
        oe[(size_t)n * R3 + k] = __float2half(t[tx][ty + 8 * i]);
    }
}

// ---------------- RMSNorm ----------------
__global__ __launch_bounds__(256) void rmsnorm_kernel(
    const float* __restrict__ x, const float* __restrict__ w, __half* __restrict__ out)
{
    int t = blockIdx.x;
    const float* xr = x + (size_t)t * DMODEL;
    int tid = threadIdx.x;
    float v0 = xr[tid], v1 = xr[tid + 256], v2 = xr[tid + 512];
    float s = v0 * v0 + v1 * v1 + v2 * v2;
    #pragma unroll
    for (int o = 16; o; o >>= 1) s += __shfl_xor_sync(0xffffffffu, s, o);
    __shared__ float red[8];
    __shared__ float scale;
    int wid = tid >> 5, lane = tid & 31;
    if (lane == 0) red[wid] = s;
    __syncthreads();
    if (tid < 32) {
        float r = (tid < 8) ? red[tid] : 0.f;
        #pragma unroll
        for (int o = 4; o; o >>= 1) r += __shfl_xor_sync(0xffffffffu, r, o);
        if (tid == 0) scale = rsqrtf(r / (float)DMODEL + 1e-5f);
    }
    __syncthreads();
    float sc = scale;
    __half* orow = out + (size_t)t * DMODEL;
    orow[tid]       = __float2half(v0 * sc * w[tid]);
    orow[tid + 256] = __float2half(v1 * sc * w[tid + 256]);
    orow[tid + 512] = __float2half(v2 * sc * w[tid + 512]);
}

// ---------------- Chunked selective scan ----------------
__global__ __launch_bounds__(64) void scan_pass1(
    const __half* __restrict__ proj, const float* __restrict__ dt_bias)
{
    int c = blockIdx.x, bh = blockIdx.y;
    int b = bh / NHEADS, h = bh % NHEADS;
    int d = threadIdx.x;
    float bias = dt_bias[h];
    const __half* base = proj + (size_t)(b * SEQ + c * CHUNK) * KPROJ;
    float Aacc = 1.f, hl = 0.f;
    #pragma unroll 4
    for (int t = 0; t < CHUNK; t++) {
        float dt = __half2float(base[(size_t)t * KPROJ + 2 * DINNER + h]);
        float u  = __half2float(base[(size_t)t * KPROJ + h * DHEAD + d]);
        float alpha = 1.f / (1.f + __expf(dt + bias));
        hl = fmaf(alpha, hl, u);
        Aacc *= alpha;
    }
    int idx = bh * NCHUNK + c;
    if (d == 0) g_cA[idx] = Aacc;
    g_cB[(size_t)idx * DHEAD + d] = hl;
}

__global__ __launch_bounds__(64) void scan_pass2()
{
    int bh = blockIdx.x;
    int d = threadIdx.x;
    // fold moe counter zeroing into this tiny kernel (runs before router)
    if (bh == 0 && d < NEXP) g_cnt[d] = 0;
    float hc = 0.f;
    #pragma unroll
    for (int c = 0; c < NCHUNK; c++) {
        int idx = bh * NCHUNK + c;
        g_carry[(size_t)idx * DHEAD + d] = hc;
        hc = fmaf(g_cA[idx], hc, g_cB[(size_t)idx * DHEAD + d]);
    }
}

__global__ __launch_bounds__(64) void scan_pass3(
    const __half* __restrict__ proj, const float* __restrict__ dt_bias,
    __half* __restrict__ y)
{
    int c = blockIdx.x, bh = blockIdx.y;
    int b = bh / NHEADS, h = bh % NHEADS;
    int d = threadIdx.x;
    float bias = dt_bias[h];
    const __half* base = proj + (size_t)(b * SEQ + c * CHUNK) * KPROJ;
    __half* yb = y + (size_t)(b * SEQ + c * CHUNK) * DINNER + h * DHEAD + d;
    float hl = g_carry[((size_t)bh * NCHUNK + c) * DHEAD + d];
    #pragma unroll 4
    for (int t = 0; t < CHUNK; t++) {
        float dt = __half2float(base[(size_t)t * KPROJ + 2 * DINNER + h]);
        float u  = __half2float(base[(size_t)t * KPROJ + h * DHEAD + d]);
        float z  = __half2float(base[(size_t)t * KPROJ + DINNER + h * DHEAD + d]);
        float alpha = 1.f / (1.f + __expf(dt + bias));
        hl = fmaf(alpha, hl, u);
        float sig = 1.f / (1.f + __expf(-z));
        float v = hl * z * sig;
        yb[(size_t)t * DINNER] = __float2half(10.f * tanhf(v * 0.1f));
    }
}

// ---------------- Router ----------------
__global__ __launch_bounds__(256) void router_kernel(
    const __half* __restrict__ x2n, const float* __restrict__ Wr)
{
    int t = blockIdx.x;
    int wid = threadIdx.x >> 5, lane = threadIdx.x & 31;
    const __half* xr = x2n + (size_t)t * DMODEL;
    float s = 0.f;
    for (int r = lane; r < DMODEL; r += 32)
        s = fmaf(__half2float(xr[r]), Wr[r * NEXP + wid], s);
    #pragma unroll
    for (int o = 16; o; o >>= 1) s += __shfl_xor_sync(0xffffffffu, s, o);
    __shared__ float logits[NEXP];
    if (lane == 0) logits[wid] = s * 2.0f;
    __syncthreads();
    if (threadIdx.x == 0) {
        float best = -1e30f; int bi = 0;
        #pragma unroll
        for (int e = 0; e < NEXP; e++)
            if (logits[e] > best) { best = logits[e]; bi = e; }
        float sec = -1e30f; int si = 0;
        #pragma unroll
        for (int e = 0; e < NEXP; e++)
            if (e != bi && logits[e] > sec) { sec = logits[e]; si = e; }
        float p0 = 1.f / (1.f + __expf(sec - best));
        float p1 = 1.f - p0;
        g_e01[t] = bi | (si << 8);
        g_p01[t] = make_float2(p0, p1);
        atomicAdd(&g_cnt[bi], 1);
        atomicAdd(&g_cnt[si], 1);
    }
}

__global__ void moe_offsets()
{
    if (threadIdx.x == 0) {
        int acc = 0;
        for (int e = 0; e < NEXP; e++) {
            g_off[e] = acc;
            g_cur[e] = acc;
            int tiles = (g_cnt[e] + 127) / 128;
            for (int i = 0; i < tiles; i++) g_tileexp[acc / 128 + i] = e;
            acc += tiles * 128;
        }
        g_off[NEXP] = acc;
        g_ntiles = acc / 128;
    }
}

__global__ __launch_bounds__(256) void moe_assign()
{
    int t = blockIdx.x * 256 + threadIdx.x;
    if (t >= NTOK) return;
    int ee = g_e01[t];
    int e0 = ee & 0xff, e1 = (ee >> 8) & 0xff;
    float2 p = g_p01[t];
    int pos0 = atomicAdd(&g_cur[e0], 1);
    g_rowtok[pos0] = t; g_rowp[pos0] = p.x; g_slot[2 * t] = pos0;
    int pos1 = atomicAdd(&g_cur[e1], 1);
    g_rowtok[pos1] = t; g_rowp[pos1] = p.y; g_slot[2 * t + 1] = pos1;
}

__global__ __launch_bounds__(256) void moe_combine()
{
    int t = blockIdx.x;
    int s0 = g_slot[2 * t], s1 = g_slot[2 * t + 1];
    const __half2* r0 = (const __half2*)(g_easgn + (size_t)s0 * R2);
    const __half2* r1 = (const __half2*)(g_easgn + (size_t)s1 * R2);
    __half2* o = (__half2*)(g_moe + (size_t)t * R2);
    int i = threadIdx.x;
    #pragma unroll
    for (int j = 0; j < 2; j++) {
        int k = i + j * 256;
        float2 a = __half22float2(r0[k]);
        float2 b = __half22float2(r1[k]);
        o[k] = __floats2half2_rn(a.x + b.x, a.y + b.y);
    }
}

// ---------------- Host launcher ----------------
extern "C" void kernel_launch(void* const* d_in, const int* in_sizes, int n_in,
                              void* d_out, int out_size)
{
    const float* x        = (const float*)d_in[0];
    const float* rms1_w   = (const float*)d_in[1];
    const float* W_in     = (const float*)d_in[2];
    const float* dt_bias  = (const float*)d_in[3];
    const float* W_out    = (const float*)d_in[4];
    const float* ls1      = (const float*)d_in[5];
    const float* rms2_w   = (const float*)d_in[6];
    const float* W_down   = (const float*)d_in[7];
    const float* W_router = (const float*)d_in[8];
    const float* G        = (const float*)d_in[9];
    const float* W_up     = (const float*)d_in[10];
    const float* ls2      = (const float*)d_in[11];
    float* out = (float*)d_out;

    __half *xn, *proj, *y, *x2n, *lat, *moe;
    __half *WinT, *WoutT, *WdownT, *GtE, *WupT;
    float *x1;
    cudaGetSymbolAddress((void**)&xn,     g_xn);
    cudaGetSymbolAddress((void**)&proj,   g_proj);
    cudaGetSymbolAddress((void**)&y,      g_y);
    cudaGetSymbolAddress((void**)&x1,     g_x1);
    cudaGetSymbolAddress((void**)&x2n,    g_x2n);
    cudaGetSymbolAddress((void**)&lat,    g_lat);
    cudaGetSymbolAddress((void**)&moe,    g_moe);
    cudaGetSymbolAddress((void**)&WinT,   g_WinT);
    cudaGetSymbolAddress((void**)&WoutT,  g_WoutT);
    cudaGetSymbolAddress((void**)&WdownT, g_WdownT);
    cudaGetSymbolAddress((void**)&GtE,    g_GtE);
    cudaGetSymbolAddress((void**)&WupT,   g_WupT);

    cudaFuncSetAttribute(hgemm<0>, cudaFuncAttributeMaxDynamicSharedMemorySize, GEMM_SMEM);
    cudaFuncSetAttribute(hgemm<1>, cudaFuncAttributeMaxDynamicSharedMemorySize, GEMM_SMEM);
    cudaFuncSetAttribute(hgemm<2>, cudaFuncAttributeMaxDynamicSharedMemorySize, GEMM_SMEM);
    cudaFuncSetAttribute(hgemm_moe, cudaFuncAttributeMaxDynamicSharedMemorySize, GEMM_SMEM);

    dim3 tb(32, 8);
    // launches 1-5, proj GEMM is launch 6 (ncu -s 5 -c 1 profiles it)
    transpose_cast<<<dim3((KPROJ + 31) / 32, DMODEL / 32), tb>>>(W_in, WinT, DMODEL, KPROJ); // 1
    rmsnorm_kernel<<<NTOK, 256>>>(x, rms1_w, xn);                                            // 2
    transpose_cast<<<dim3(DMODEL / 32, DINNER / 32), tb>>>(W_out, WoutT, DINNER, DMODEL);    // 3
    transpose_cast<<<dim3(R3 / 32, DMODEL / 32), tb>>>(W_down, WdownT, DMODEL, R3);          // 4
    transpose_cast<<<dim3(DMODEL / 32, R2 / 32), tb>>>(W_up, WupT, R2, DMODEL);              // 5
    // proj = xn @ W_in  [8192, 6192]  (profiled)
    hgemm<0><<<dim3((KPROJ + 127) / 128, NTOK / 128), 256, GEMM_SMEM>>>(
        xn, WinT, proj, KPROJ, DMODEL, nullptr, nullptr);                                    // 6
    transpose_cast_G<<<dim3(R2 / 32, R3 / 32, NEXP), tb>>>(G, GtE);

    scan_pass1<<<dim3(NCHUNK, BATCH * NHEADS), 64>>>(proj, dt_bias);
    scan_pass2<<<BATCH * NHEADS, 64>>>();
    scan_pass3<<<dim3(NCHUNK, BATCH * NHEADS), 64>>>(proj, dt_bias, y);
    hgemm<1><<<dim3(DMODEL / 128, NTOK / 128), 256, GEMM_SMEM>>>(
        y, WoutT, x1, DMODEL, DINNER, x, ls1);
    rmsnorm_kernel<<<NTOK, 256>>>(x1, rms2_w, x2n);
    hgemm<2><<<dim3(R3 / 128, NTOK / 128), 256, GEMM_SMEM>>>(
        x2n, WdownT, lat, R3, DMODEL, nullptr, nullptr);
    router_kernel<<<NTOK, 256>>>(x2n, W_router);
    moe_offsets<<<1, 32>>>();
    moe_assign<<<(NTOK + 255) / 256, 256>>>();
    hgemm_moe<<<dim3(R2 / 128, MAXTILES), 256, GEMM_SMEM>>>();
    moe_combine<<<NTOK, 256>>>();
    hgemm<1><<<dim3(DMODEL / 128, NTOK / 128), 256, GEMM_SMEM>>>(
        moe, WupT, out, DMODEL, R2, x1, ls2);
}